// round 17
// baseline (speedup 1.0000x reference)
#include <cuda_runtime.h>
#include <cuda_bf16.h>
#include <stdint.h>

#define BB 32
#define KK 512
#define CC 32
#define NBLK 148
#define NCB 128
#define NTH 640          // 4 compute warps + 16 store warps
#define NPH 4            // phases: 8 batches each
#define NSTEP 32         // 4 phases x 8 chunks of 16 rows
#define DSMEM 57600

// Scratch (no allocations allowed)
__device__ float    g_U4[BB * 4 * CC * KK];   // [((b*4+quarter)*32+o)*512+k]  8MB
__device__ float4   g_Vp4[BB * 4 * CC * 128]; // [((b*4+tile)*32+o)*128+j4]    8MB
__device__ float    g_s[BB * CC];
__device__ unsigned g_cnt[BB];
__device__ unsigned g_sflag[BB];
__device__ unsigned g_done;

union F2U { float2 f; unsigned long long u; };
union F4U { float4 f; unsigned long long u[2]; };

__device__ __forceinline__ unsigned long long ffma2(unsigned long long a,
                                                    unsigned long long b,
                                                    unsigned long long c) {
    unsigned long long d;
    asm("fma.rn.f32x2 %0, %1, %2, %3;" : "=l"(d) : "l"(a), "l"(b), "l"(c));
    return d;
}
__device__ __forceinline__ unsigned long long pack2(float v) {
    unsigned long long r;
    asm("mov.b64 %0, {%1, %1};" : "=l"(r) : "f"(v));
    return r;
}
__device__ __forceinline__ void cp16(uint32_t smem_addr, const void* gptr) {
    asm volatile("cp.async.cg.shared.global [%0], [%1], 16;"
                 :: "r"(smem_addr), "l"(gptr));
}
__device__ __forceinline__ unsigned ld_acq(const unsigned* p) {
    unsigned v;
    asm volatile("ld.acquire.gpu.global.u32 %0, [%1];" : "=r"(v) : "l"(p) : "memory");
    return v;
}
__device__ __forceinline__ void red_rel_add(unsigned* p, unsigned v) {
    asm volatile("red.release.gpu.global.add.u32 [%0], %1;" :: "l"(p), "r"(v) : "memory");
}
#define BAR_C() asm volatile("bar.sync 1, 128;" ::: "memory")
#define BAR_S() asm volatile("bar.sync 2, 512;" ::: "memory")

// float4 base of 16-row subchunk for (block g, step): unit u=g+128p,
// b=u>>4, sub=u&15, tile=sub>>2 (128 rows), quarter=sub&3 (128 cols)
__device__ __forceinline__ size_t stepbase_f4(int g, int step) {
    int u = g + 128 * (step >> 3);
    int b = u >> 4, sub = u & 15;
    int tile = sub >> 2, quarter = sub & 3;
    return ((size_t)(b * KK + tile * 128 + (step & 7) * 16)) * 128 + quarter * 32;
}

__global__ __launch_bounds__(NTH, 1) void fused4(const float* __restrict__ x,
                                                 const float* __restrict__ wc,
                                                 const float* __restrict__ bc,
                                                 const float* __restrict__ wr,
                                                 const float* __restrict__ br,
                                                 float4* __restrict__ out) {
    extern __shared__ char smem[];
    float4* xs4    = (float4*)(smem);           // 2 x 512 f4 = 16KB
    float4* wcs    = (float4*)(smem + 16384);   // [f*32+o]     16KB
    float*  wr_s   = (float*) (smem + 32768);   // [row*32+o]   16KB
    float*  u_part = (float*) (smem + 49152);   // [(r*32+o)*4+w] 8KB

    const int g = blockIdx.x;
    const int t = threadIdx.x;

    if (t < 128) {
        // ==================== COMPUTE (warps 0-3) ====================
        if (g < NCB) {
            const int ct = t, o = t & 31, w = t >> 5;
            const float4* x4  = (const float4*)x;
            const float4* wc4 = (const float4*)wc;
            const uint32_t sa = (uint32_t)__cvta_generic_to_shared(xs4);

            // prefetch step 0
            {
                const size_t base = stepbase_f4(g, 0);
#pragma unroll
                for (int i = 0; i < 4; i++) {
                    int idx = ct + 128 * i;
                    cp16(sa + (uint32_t)idx * 16u,
                         x4 + base + (idx >> 5) * 128 + (idx & 31));
                }
                asm volatile("cp.async.commit_group;");
            }

            unsigned long long Vacc[16];

            for (int p = 0; p < NPH; p++) {
                const int u = g + 128 * p;
                const int b = u >> 4, sub = u & 15;
                const int tile = sub >> 2, quarter = sub & 3;
                const int i0 = tile * 128;

                for (int n = 0; n < 8; n++) {
                    const int step = p * 8 + n, buf = step & 1;
                    asm volatile("cp.async.wait_group 0;" ::: "memory");
                    BAR_C();

                    if (step + 1 < NSTEP) {
                        const size_t base = stepbase_f4(g, step + 1);
                        const uint32_t dst = sa + (uint32_t)((buf ^ 1) * 8192);
#pragma unroll
                        for (int i = 0; i < 4; i++) {
                            int idx = ct + 128 * i;
                            cp16(dst + (uint32_t)idx * 16u,
                                 x4 + base + (idx >> 5) * 128 + (idx & 31));
                        }
                        asm volatile("cp.async.commit_group;");
                    }

                    if (n == 0) {
                        // stage w_row rows i0..i0+127 and w_col quarter-slice
#pragma unroll
                        for (int i = 0; i < 32; i++) {
                            int idx = ct + 128 * i;
                            wr_s[idx] = wr[(idx & 31) * KK + i0 + (idx >> 5)];
                        }
#pragma unroll
                        for (int i = 0; i < 8; i++) {
                            int idx = ct + 128 * i;
                            wcs[(idx >> 5) * 32 + (idx & 31)] =
                                wc4[(idx & 31) * 128 + quarter * 32 + (idx >> 5)];
                        }
#pragma unroll
                        for (int q = 0; q < 16; q++) Vacc[q] = 0ull;
                        BAR_C();
                    }

                    const float4* xr = xs4 + buf * 512;
#pragma unroll
                    for (int r = 0; r < 16; r++) {
                        const unsigned long long wr2 = pack2(wr_s[(n * 16 + r) * 32 + o]);
                        const float4* xrow = xr + r * 32;
                        unsigned long long ua = 0ull, ub = 0ull;
#pragma unroll
                        for (int q = 0; q < 8; q++) {
                            F4U xv; xv.f = xrow[w + 4 * q];           // broadcast
                            F4U cw; cw.f = wcs[(w + 4 * q) * 32 + o];
                            Vacc[2 * q]     = ffma2(wr2, xv.u[0], Vacc[2 * q]);
                            Vacc[2 * q + 1] = ffma2(wr2, xv.u[1], Vacc[2 * q + 1]);
                            ua = ffma2(cw.u[0], xv.u[0], ua);
                            ub = ffma2(cw.u[1], xv.u[1], ub);
                        }
                        F2U us; us.u = ua; F2U ut; ut.u = ub;
                        u_part[(r * 32 + o) * 4 + w] =
                            (us.f.x + us.f.y) + (ut.f.x + ut.f.y);
                    }
                    BAR_C();

                    // cross-warp U reduce -> quarter partial (k-major per o)
                    {
                        const int oo = ct >> 2, kl = ct & 3;
                        const size_t ub_ = ((size_t)((b * 4 + quarter) * 32 + oo)) * KK
                                           + i0 + n * 16;
#pragma unroll
                        for (int ki = 0; ki < 4; ki++) {
                            int rr = kl + 4 * ki;
                            float4 up = ((const float4*)u_part)[rr * 32 + oo];
                            g_U4[ub_ + rr] = (up.x + up.y) + (up.z + up.w);
                        }
                    }
                }

                // V quarter-partial writeback
                {
                    float4* Vg = g_Vp4 + ((size_t)((b * 4 + tile) * 32 + o)) * 128
                                 + quarter * 32;
#pragma unroll
                    for (int q = 0; q < 8; q++) {
                        F4U v; v.u[0] = Vacc[2 * q]; v.u[1] = Vacc[2 * q + 1];
                        Vg[w + 4 * q] = v.f;
                    }
                }
                __threadfence();
                BAR_C();
                if (ct == 0) red_rel_add(&g_cnt[b], 1);

                // s-reduction duty: block 4*db reduces batch db at phase db>>3
                if ((g & 3) == 0 && (g >> 5) == p) {
                    const int db = g >> 2;
                    if (ct == 0) { while (ld_acq(&g_cnt[db]) < 16) __nanosleep(64); }
                    BAR_C();
                    const int wq = ct >> 5, l = ct & 31;
#pragma unroll
                    for (int oi = 0; oi < 8; oi++) {
                        const int oo = wq * 8 + oi;
                        const float brv = br[oo], bcv = bc[oo];
                        float acc = 0.f;
#pragma unroll
                        for (int jj = 0; jj < 4; jj++) {
                            const int j4 = l + 32 * jj;
                            float4 V = make_float4(0, 0, 0, 0);
#pragma unroll
                            for (int tt = 0; tt < 4; tt++) {
                                float4 v = g_Vp4[((size_t)((db * 4 + tt) * 32 + oo)) * 128 + j4];
                                V.x += v.x; V.y += v.y; V.z += v.z; V.w += v.w;
                            }
                            float4 U = make_float4(0, 0, 0, 0);
#pragma unroll
                            for (int qq = 0; qq < 4; qq++) {
                                float4 uu = *(const float4*)&g_U4[((size_t)((db * 4 + qq) * 32 + oo)) * KK + 4 * j4];
                                U.x += uu.x; U.y += uu.y; U.z += uu.z; U.w += uu.w;
                            }
                            acc += (V.x + brv) * (U.x + bcv) + (V.y + brv) * (U.y + bcv)
                                 + (V.z + brv) * (U.z + bcv) + (V.w + brv) * (U.w + bcv);
                        }
#pragma unroll
                        for (int m = 16; m > 0; m >>= 1)
                            acc += __shfl_xor_sync(0xffffffffu, acc, m);
                        if (l == 0) g_s[db * CC + oo] = acc;
                    }
                    __threadfence();
                    BAR_C();
                    if (ct == 0) red_rel_add(&g_sflag[db], 1);
                }
            }
        }
    } else {
        // ==================== STORE (warps 4-19) ====================
        const int ts = t - 128;
        for (int P = g; P < BB * CC; P += NBLK) {
            const int b = P >> 5;
            if (ts == 0) { while (ld_acq(&g_sflag[b]) < 1) __nanosleep(128); }
            BAR_S();
            const float sv = __ldcg(&g_s[P]);
            const float4 val = make_float4(sv, sv, sv, sv);
            float4* p4 = out + (size_t)P * 65536 + ts;
#pragma unroll 32
            for (int i = 0; i < 128; i++) p4[i * 512] = val;
        }
    }

    // ---- done barrier + counter reset (deterministic graph replays) ----
    __threadfence();
    __syncthreads();
    if (t == 0) red_rel_add(&g_done, 1);
    if (g == NBLK - 1 && t == 0) {
        while (ld_acq(&g_done) < NBLK) __nanosleep(128);
        for (int i = 0; i < BB; i++) { g_cnt[i] = 0; g_sflag[i] = 0; }
        g_done = 0;
        __threadfence();
    }
}

extern "C" void kernel_launch(void* const* d_in, const int* in_sizes, int n_in,
                              void* d_out, int out_size) {
    const float* x  = (const float*)d_in[0];
    const float* wc = (const float*)d_in[1];
    const float* bc = (const float*)d_in[2];
    const float* wr = (const float*)d_in[3];
    const float* br = (const float*)d_in[4];

    static bool attr_set = false;
    if (!attr_set) {
        cudaFuncSetAttribute(fused4, cudaFuncAttributeMaxDynamicSharedMemorySize, DSMEM);
        attr_set = true;
    }
    fused4<<<NBLK, NTH, DSMEM>>>(x, wc, bc, wr, br, (float4*)d_out);
}